// round 17
// baseline (speedup 1.0000x reference)
#include <cuda_runtime.h>
#include <math.h>
#include <stdint.h>

#define NTOK   2048
#define DMODEL 256
#define DFF    1024
#define NHEAD  8
#define DHEAD  32
#define KWIN   5
#define NNBR   125   // 5*5*5

// ---------------- scratch (device globals; no allocations allowed) ----------
__device__ float    g_v [NTOK * DMODEL];
__device__ float    g_at[NTOK * DMODEL];
__device__ float    g_h [NTOK * DMODEL];
__device__ float    g_fa[NTOK * DFF];
__device__ float    g_rs1[NTOK];
__device__ float    g_ssp[8 * NTOK];               // per-row sumsq partials of h
__device__ uint32_t g_qh[NTOK * (DMODEL / 2)];     // Q bf16, channel-paired
__device__ uint32_t g_kh[NTOK * (DMODEL / 2)];     // K bf16, channel-paired
__device__ uint32_t g_w1h[(DMODEL / 2) * DFF];     // W1 bf16, K-paired
__device__ uint32_t g_w2h[(DMODEL / 2) * DFF];     // W2 bf16, K-paired

// ---------------- helpers ----------------------------------------------------
__device__ __forceinline__ void mma_tf32(float d[4], const uint32_t a[4], const uint32_t b[2]) {
    asm volatile(
        "mma.sync.aligned.m16n8k8.row.col.f32.tf32.tf32.f32 "
        "{%0,%1,%2,%3},{%4,%5,%6,%7},{%8,%9},{%0,%1,%2,%3};"
        : "+f"(d[0]), "+f"(d[1]), "+f"(d[2]), "+f"(d[3])
        : "r"(a[0]), "r"(a[1]), "r"(a[2]), "r"(a[3]), "r"(b[0]), "r"(b[1]));
}

__device__ __forceinline__ void mma_bf16(float d[4], const uint32_t a[4], const uint32_t b[2]) {
    asm volatile(
        "mma.sync.aligned.m16n8k16.row.col.f32.bf16.bf16.f32 "
        "{%0,%1,%2,%3},{%4,%5,%6,%7},{%8,%9},{%0,%1,%2,%3};"
        : "+f"(d[0]), "+f"(d[1]), "+f"(d[2]), "+f"(d[3])
        : "r"(a[0]), "r"(a[1]), "r"(a[2]), "r"(a[3]), "r"(b[0]), "r"(b[1]));
}

__device__ __forceinline__ uint32_t pack_bf16(float lo, float hi) {
    uint32_t r;
    asm("cvt.rn.bf16x2.f32 %0, %1, %2;" : "=r"(r) : "f"(hi), "f"(lo));
    return r;
}

__device__ __forceinline__ void cp_async16(void* smem_dst, const void* gsrc) {
    uint32_t s = (uint32_t)__cvta_generic_to_shared(smem_dst);
    asm volatile("cp.async.cg.shared.global [%0], [%1], 16;" :: "r"(s), "l"(gsrc));
}
__device__ __forceinline__ void cp_commit() { asm volatile("cp.async.commit_group;"); }

#define ASTR 36    // fp32 A frag banks: 4g+tig -> permutation
#define BSTR 72    // fp32 B frag banks: 8tig+g -> permutation
#define NSTG 3     // pipeline stages
#define AH_STR 20  // bf16 A (words/row): banks 4g+tig
#define BH_STR 72  // bf16 B (words/kpair-row): banks 8tig+g

// ---------------- W1/W2 -> bf16 (K-paired) conversion -------------------------
__global__ __launch_bounds__(256) void cvt_w12_k(
    const float* __restrict__ w1, const float* __restrict__ w2,
    uint32_t* __restrict__ w1h, uint32_t* __restrict__ w2h) {
    const int idx = blockIdx.x * 256 + threadIdx.x;
    const int kp = idx >> 10, n = idx & 1023;
    const size_t o0 = (size_t)(2 * kp) * DFF + n;
    const size_t o1 = o0 + DFF;
    w1h[idx] = pack_bf16(w1[o0], w1[o1]);
    w2h[idx] = pack_bf16(w2[o0], w2[o1]);
}

// ---------------- RMS scale: one warp per token ------------------------------
__global__ __launch_bounds__(256) void rms_scale_k(const float* __restrict__ x,
                                                   float* __restrict__ rscale) {
    const int warp = threadIdx.x >> 5;
    const int lane = threadIdx.x & 31;
    const int token = blockIdx.x * 8 + warp;
    const float4 a = *(const float4*)&x[(size_t)token * DMODEL + lane * 4];
    const float4 b = *(const float4*)&x[(size_t)token * DMODEL + 128 + lane * 4];
    float s = a.x * a.x + a.y * a.y + a.z * a.z + a.w * a.w
            + b.x * b.x + b.y * b.y + b.z * b.z + b.w * b.w;
    #pragma unroll
    for (int o = 16; o; o >>= 1) s += __shfl_xor_sync(0xffffffffu, s, o);
    if (lane == 0) rscale[token] = rsqrtf(s * (1.0f / DMODEL) + 1e-6f);
}

// ---------------- TF32 GEMM v7: 32x64x32, 128 thr, 3-stage, conflict-free ----
// PACKQK: z<2 outputs written as channel-paired bf16 (Cqh/Ckh).
template<bool SCALED, bool PACKQK>
__global__ __launch_bounds__(128) void gemm_v7(
    const float* __restrict__ A,
    const float* __restrict__ rs, const float* __restrict__ nw,
    const float* __restrict__ B0, const float* __restrict__ B1, const float* __restrict__ B2,
    const float* __restrict__ bias0, const float* __restrict__ bias1, const float* __restrict__ bias2,
    const float* __restrict__ res,
    float* __restrict__ C0, float* __restrict__ C1, float* __restrict__ C2,
    uint32_t* __restrict__ Cqh, uint32_t* __restrict__ Ckh,
    float* __restrict__ ssp,
    int N, int K) {

    const int z = blockIdx.z;
    const float* B    = (z == 0) ? B0    : (z == 1) ? B1    : B2;
    const float* bias = (z == 0) ? bias0 : (z == 1) ? bias1 : bias2;
    float*       C    = (z == 0) ? C0    : (z == 1) ? C1    : C2;

    __shared__ float As[NSTG][32 * ASTR];
    __shared__ float Bs[NSTG][32 * BSTR];
    __shared__ float nws[DMODEL];
    __shared__ float rsc[32];

    const int tid  = threadIdx.x;
    const int warp = tid >> 5;
    const int lane = tid & 31;
    const int g    = lane >> 2;
    const int tig  = lane & 3;
    const int warpRow = (warp & 1) * 16;
    const int warpCol = (warp >> 1) * 32;
    const int bm = blockIdx.y * 32;
    const int bn = blockIdx.x * 64;

    float sc0 = 1.f, sc1 = 1.f;
    if (SCALED) {
        for (int i = tid * 4; i < K; i += 512)
            *(float4*)&nws[i] = *(const float4*)&nw[i];
        if (tid < 32) rsc[tid] = rs[bm + tid];
        __syncthreads();
        sc0 = rsc[warpRow + g];
        sc1 = rsc[warpRow + g + 8];
    }

    float acc[4][4];
    #pragma unroll
    for (int nt = 0; nt < 4; nt++)
        #pragma unroll
        for (int i = 0; i < 4; i++) acc[nt][i] = 0.f;

    const int nkt = K >> 5;

    auto load_tile = [&](int st, int k0) {
        #pragma unroll
        for (int j = 0; j < 2; j++) {
            const int c = tid + 128 * j;
            const int row = c >> 3, kc = (c & 7) * 4;
            cp_async16(&As[st][row * ASTR + kc], &A[(size_t)(bm + row) * K + k0 + kc]);
        }
        #pragma unroll
        for (int j = 0; j < 4; j++) {
            const int c = tid + 128 * j;
            const int row = c >> 4, nc = (c & 15) * 4;
            cp_async16(&Bs[st][row * BSTR + nc], &B[(size_t)(k0 + row) * N + bn + nc]);
        }
        cp_commit();
    };

    load_tile(0, 0);
    load_tile(1, 32);

    for (int kt = 0; kt < nkt; kt++) {
        const int st = kt % NSTG;
        if (kt + 2 < nkt) load_tile((kt + 2) % NSTG, (kt + 2) * 32);
        if (kt + 2 < nkt)      asm volatile("cp.async.wait_group 2;");
        else if (kt + 1 < nkt) asm volatile("cp.async.wait_group 1;");
        else                   asm volatile("cp.async.wait_group 0;");
        __syncthreads();

        const float* Ab = As[st];
        const float* Bb = Bs[st];
        const int kb = kt * 32;
        #pragma unroll
        for (int s = 0; s < 4; s++) {
            const int r0 = warpRow + g;
            float a0 = Ab[r0 * ASTR + 8 * s + tig];
            float a1 = Ab[(r0 + 8) * ASTR + 8 * s + tig];
            float a2 = Ab[r0 * ASTR + 8 * s + 4 + tig];
            float a3 = Ab[(r0 + 8) * ASTR + 8 * s + 4 + tig];
            if (SCALED) {
                const float w0 = nws[kb + 8 * s + tig];
                const float w1 = nws[kb + 8 * s + 4 + tig];
                a0 *= sc0 * w0; a1 *= sc1 * w0; a2 *= sc0 * w1; a3 *= sc1 * w1;
            }
            uint32_t ua[4] = {__float_as_uint(a0), __float_as_uint(a1),
                              __float_as_uint(a2), __float_as_uint(a3)};
            uint32_t b[4][2];
            #pragma unroll
            for (int nt = 0; nt < 4; nt++) {
                const int c = warpCol + nt * 8 + g;
                b[nt][0] = __float_as_uint(Bb[(8 * s + tig) * BSTR + c]);
                b[nt][1] = __float_as_uint(Bb[(8 * s + 4 + tig) * BSTR + c]);
            }
            #pragma unroll
            for (int nt = 0; nt < 4; nt++) mma_tf32(acc[nt], ua, b[nt]);
        }
        __syncthreads();
    }

    const int r0 = bm + warpRow + g;
    const int r1 = r0 + 8;

    if (PACKQK && z < 2) {
        uint32_t* Ch = (z == 0) ? Cqh : Ckh;
        #pragma unroll
        for (int nt = 0; nt < 4; nt++) {
            const int col = bn + warpCol + nt * 8 + 2 * tig;
            const float b0 = bias[col], b1 = bias[col + 1];
            Ch[(size_t)r0 * (DMODEL / 2) + (col >> 1)] =
                pack_bf16(acc[nt][0] + b0, acc[nt][1] + b1);
            Ch[(size_t)r1 * (DMODEL / 2) + (col >> 1)] =
                pack_bf16(acc[nt][2] + b0, acc[nt][3] + b1);
        }
        return;
    }

    float s0 = 0.f, s1 = 0.f;
    #pragma unroll
    for (int nt = 0; nt < 4; nt++) {
        const int col = bn + warpCol + nt * 8 + 2 * tig;
        float b0 = 0.f, b1 = 0.f;
        if (bias) { b0 = bias[col]; b1 = bias[col + 1]; }
        float2 o0 = make_float2(acc[nt][0] + b0, acc[nt][1] + b1);
        float2 o1 = make_float2(acc[nt][2] + b0, acc[nt][3] + b1);
        if (res) {
            const float2 q0 = *(const float2*)&res[(size_t)r0 * N + col];
            const float2 q1 = *(const float2*)&res[(size_t)r1 * N + col];
            o0.x += q0.x; o0.y += q0.y;
            o1.x += q1.x; o1.y += q1.y;
        }
        s0 += o0.x * o0.x + o0.y * o0.y;
        s1 += o1.x * o1.x + o1.y * o1.y;
        *(float2*)&C[(size_t)r0 * N + col] = o0;
        *(float2*)&C[(size_t)r1 * N + col] = o1;
    }
    if (ssp) {
        s0 += __shfl_xor_sync(0xffffffffu, s0, 1);
        s0 += __shfl_xor_sync(0xffffffffu, s0, 2);
        s1 += __shfl_xor_sync(0xffffffffu, s1, 1);
        s1 += __shfl_xor_sync(0xffffffffu, s1, 2);
        if (tig == 0) {
            const int p = blockIdx.x * 2 + (warp >> 1);
            ssp[p * NTOK + r0] = s0;
            ssp[p * NTOK + r1] = s1;
        }
    }
}

// ---------------- gate GEMM bf16: silu(A'@W1)*(A'@W2), m16n8k16 --------------
__global__ __launch_bounds__(128) void gate_h(
    const float* __restrict__ A,
    const float* __restrict__ ssp, const float* __restrict__ nw,
    const uint32_t* __restrict__ W1h, const uint32_t* __restrict__ W2h,
    float* __restrict__ C, int N, int K) {

    __shared__ float    nws[DMODEL];
    __shared__ float    rsc[32];
    __shared__ uint32_t Ah [NSTG][32 * AH_STR];
    __shared__ uint32_t B1h[NSTG][16 * BH_STR];
    __shared__ uint32_t B2h[NSTG][16 * BH_STR];

    const int tid  = threadIdx.x;
    const int warp = tid >> 5;
    const int lane = tid & 31;
    const int g    = lane >> 2;
    const int tig  = lane & 3;
    const int warpRow = (warp & 1) * 16;
    const int warpCol = (warp >> 1) * 32;
    const int bm = blockIdx.y * 32;
    const int bn = blockIdx.x * 64;

    for (int i = tid * 4; i < K; i += 512)
        *(float4*)&nws[i] = *(const float4*)&nw[i];
    if (tid < 32) {
        const int row = bm + tid;
        float s = 0.f;
        #pragma unroll
        for (int p = 0; p < 8; p++) s += ssp[p * NTOK + row];
        rsc[tid] = rsqrtf(s * (1.0f / DMODEL) + 1e-6f);
    }
    __syncthreads();

    float acc1[4][4], acc2[4][4];
    #pragma unroll
    for (int nt = 0; nt < 4; nt++)
        #pragma unroll
        for (int i = 0; i < 4; i++) { acc1[nt][i] = 0.f; acc2[nt][i] = 0.f; }

    const int nkt = K >> 5;

    auto load_tile = [&](int st, int k0) {
        const int arow = tid >> 2;
        const int aq   = tid & 3;
        const float sc = rsc[arow];
        #pragma unroll
        for (int j = 0; j < 2; j++) {
            const int kc = aq * 8 + j * 4;
            const float4 xv = *(const float4*)&A[(size_t)(bm + arow) * K + k0 + kc];
            const float w0 = nws[k0 + kc],     w1 = nws[k0 + kc + 1];
            const float w2 = nws[k0 + kc + 2], w3 = nws[k0 + kc + 3];
            Ah[st][arow * AH_STR + (kc >> 1)]     = pack_bf16(xv.x * sc * w0, xv.y * sc * w1);
            Ah[st][arow * AH_STR + (kc >> 1) + 1] = pack_bf16(xv.z * sc * w2, xv.w * sc * w3);
        }
        const int kp0 = k0 >> 1;
        #pragma unroll
        for (int j = 0; j < 2; j++) {
            const int c = tid + 128 * j;
            const int r = c >> 4, nc4 = (c & 15) * 4;
            const size_t off = (size_t)(kp0 + r) * N + bn + nc4;
            cp_async16(&B1h[st][r * BH_STR + nc4], &W1h[off]);
            cp_async16(&B2h[st][r * BH_STR + nc4], &W2h[off]);
        }
        cp_commit();
    };

    load_tile(0, 0);
    load_tile(1, 32);

    for (int kt = 0; kt < nkt; kt++) {
        const int st = kt % NSTG;
        if (kt + 2 < nkt) load_tile((kt + 2) % NSTG, (kt + 2) * 32);
        if (kt + 2 < nkt)      asm volatile("cp.async.wait_group 2;");
        else if (kt + 1 < nkt) asm volatile("cp.async.wait_group 1;");
        else                   asm volatile("cp.async.wait_group 0;");
        __syncthreads();

        const uint32_t* Ab  = Ah[st];
        const uint32_t* B1b = B1h[st];
        const uint32_t* B2b = B2h[st];
        #pragma unroll
        for (int s = 0; s < 2; s++) {
            const int r0 = warpRow + g;
            uint32_t a[4];
            a[0] = Ab[r0 * AH_STR + 8 * s + tig];
            a[1] = Ab[(r0 + 8) * AH_STR + 8 * s + tig];
            a[2] = Ab[r0 * AH_STR + 8 * s + 4 + tig];
            a[3] = Ab[(r0 + 8) * AH_STR + 8 * s + 4 + tig];
            uint32_t b1[4][2], b2[4][2];
            #pragma unroll
            for (int nt = 0; nt < 4; nt++) {
                const int c = warpCol + nt * 8 + g;
                b1[nt][0] = B1b[(8 * s + tig) * BH_STR + c];
                b1[nt][1] = B1b[(8 * s + 4 + tig) * BH_STR + c];
                b2[nt][0] = B2b[(8 * s + tig) * BH_STR + c];
                b2[nt][1] = B2b[(8 * s + 4 + tig) * BH_STR + c];
            }
            #pragma unroll
            for (int nt = 0; nt < 4; nt++) {
                mma_bf16(acc1[nt], a, b1[nt]);
                mma_bf16(acc2[nt], a, b2[nt]);
            }
        }
        __syncthreads();
    }

    const int r0 = bm + warpRow + g;
    const int r1 = r0 + 8;
    #pragma unroll
    for (int nt = 0; nt < 4; nt++) {
        const int col = bn + warpCol + nt * 8 + 2 * tig;
        #pragma unroll
        for (int half = 0; half < 2; half++) {
            const int row = (half == 0) ? r0 : r1;
            const float a0 = acc1[nt][half * 2 + 0];
            const float a1 = acc1[nt][half * 2 + 1];
            float2 o;
            o.x = a0 / (1.f + __expf(-a0)) * acc2[nt][half * 2 + 0];
            o.y = a1 / (1.f + __expf(-a1)) * acc2[nt][half * 2 + 1];
            *(float2*)&C[(size_t)row * N + col] = o;
        }
    }
}

// ---------------- NA3D v4: bf16 tensor-core attention -------------------------
#define KHSTR 20   // Kh/Qh word stride: banks 4g+tig
#define VHSTR 36   // Vh word stride: banks 4tig+g
#define PHSTR 164  // Ph word stride: banks 4g+tig

__global__ __launch_bounds__(256) void na3d_v4(
    const uint32_t* __restrict__ qh, const uint32_t* __restrict__ kbh,
    const float* __restrict__ v, float* __restrict__ out) {

    extern __shared__ uint32_t smu[];
    uint32_t* KVu = smu;                    // Kh 320*20=6400 / Vh 160*36=5760
    uint32_t* Qh  = smu + 6400;             // 16*20 = 320
    uint32_t* Ph  = Qh + 320;               // 16*164 = 2624
    float* red  = (float*)(Ph + 2624);      // 128
    float* Gm   = red + 128;                // 16
    float* Ssum = Gm + 16;                  // 16
    float* redO = Ssum + 16;                // 512
    int*  rinfo = (int*)(redO + 512);       // 16

    const int tile = blockIdx.x, head = blockIdx.y;
    const int t  = tile >> 4;
    const int th0 = ((tile >> 2) & 3) * 4;
    const int tw0 = (tile & 3) * 4;
    const int h_base = min(max(th0 - 2, 0), 8);
    const int w_base = min(max(tw0 - 2, 0), 8);
    const int tlmin  = max(0, 4 - t);
    const float scale = 0.17677669529663687f;

    const int tid = threadIdx.x;
    const int wp  = tid >> 5;
    const int l   = tid & 31;
    const int gr  = l >> 2;
    const int tig = l & 3;

    // ---- stage Kh (cp.async), Qh, rinfo ----
    #pragma unroll
    for (int j = 0; j < 5; j++) {
        const int u = tid + 256 * j;                 // 0..1279: slot x 4 chunks
        const int slot = u >> 2, w4 = (u & 3) * 4;
        const int tl = slot >> 6, rem = slot & 63;
        const int tn = max(t - 4 + tl, 0);
        const int hn = h_base + (rem >> 3), wn = w_base + (rem & 7);
        const int tokn = (tn * 16 + hn) * 16 + wn;
        cp_async16(&KVu[slot * KHSTR + w4],
                   &kbh[(size_t)tokn * (DMODEL / 2) + head * 16 + w4]);
    }
    cp_commit();
    if (tid < 16) {
        const int hr = th0 + (tid >> 2), wr = tw0 + (tid & 3);
        const int hoff = min(max(hr - 2, 0), 11) - h_base;
        const int woff = min(max(wr - 2, 0), 11) - w_base;
        const int tok  = (t * 16 + hr) * 16 + wr;
        rinfo[tid] = hoff | (woff << 4) | (tok << 8);
    }
    if (tid < 64) {
        const int r = tid >> 2, w4 = (tid & 3) * 4;
        const int hr = th0 + (r >> 2), wr = tw0 + (r & 3);
        const int tok = (t * 16 + hr) * 16 + wr;
        *(uint4*)&Qh[r * KHSTR + w4] =
            *(const uint4*)&qh[(size_t)tok * (DMODEL / 2) + head * 16 + w4];
    }
    asm volatile("cp.async.wait_group 0;");
    __syncthreads();

    // ---- S^T = K @ Q^T (bf16): m=320, n=16, k=32 (2 k16-steps) ----
    uint32_t bf[2][2][2];
    #pragma unroll
    for (int nt = 0; nt < 2; nt++)
        #pragma unroll
        for (int s = 0; s < 2; s++) {
            bf[nt][s][0] = Qh[(nt * 8 + gr) * KHSTR + 8 * s + tig];
            bf[nt][s][1] = Qh[(nt * 8 + gr) * KHSTR + 8 * s + 4 + tig];
        }

    const int nmt = (wp < 4) ? 3 : 2;
    const int m0s[3] = {wp * 16, (wp + 8) * 16, (wp + 16) * 16};
    float sacc[3][2][4];
    for (int mi = 0; mi < 3; mi++)
        #pragma unroll
        for (int nt = 0; nt < 2; nt++)
            #pragma unroll
            for (int i = 0; i < 4; i++) sacc[mi][nt][i] = 0.f;

    for (int mi = 0; mi < nmt; mi++) {
        const int m0 = m0s[mi];
        #pragma unroll
        for (int s = 0; s < 2; s++) {
            uint32_t a[4];
            a[0] = KVu[(m0 + gr) * KHSTR + 8 * s + tig];
            a[1] = KVu[(m0 + gr + 8) * KHSTR + 8 * s + tig];
            a[2] = KVu[(m0 + gr) * KHSTR + 8 * s + 4 + tig];
            a[3] = KVu[(m0 + gr + 8) * KHSTR + 8 * s + 4 + tig];
            mma_bf16(sacc[mi][0], a, bf[0][s]);
            mma_bf16(sacc[mi][1], a, bf[1][s]);
        }
    }

    // ---- mask + scale; per-token partial max ----
    int ho[4], wo[4];
    #pragma unroll
    for (int i = 0; i < 4; i++) {
        const int tk = (i >> 1) * 8 + 2 * tig + (i & 1);
        const int inf = rinfo[tk];
        ho[i] = inf & 15;
        wo[i] = (inf >> 4) & 15;
    }
    float pm[4] = {-INFINITY, -INFINITY, -INFINITY, -INFINITY};
    for (int mi = 0; mi < nmt; mi++) {
        const int s0 = m0s[mi] + gr, s1 = s0 + 8;
        const int tl0 = s0 >> 6, sh0 = (s0 >> 3) & 7, sw0 = s0 & 7;
        const int tl1 = s1 >> 6, sh1 = (s1 >> 3) & 7, sw1 = s1 & 7;
        #pragma unroll
        for (int nt = 0; nt < 2; nt++) {
            #pragma unroll
            for (int ci = 0; ci < 4; ci++) {
                const int pi = nt * 2 + (ci & 1);
                const int sh = (ci < 2) ? sh0 : sh1;
                const int sw = (ci < 2) ? sw0 : sw1;
                const int tl = (ci < 2) ? tl0 : tl1;
                const bool valid = (tl >= tlmin) &&
                                   ((unsigned)(sh - ho[pi]) <= 4u) &&
                                   ((unsigned)(sw - wo[pi]) <= 4u);
                const float sv = valid ? sacc[mi][nt][ci] * scale : -INFINITY;
                sacc[mi][nt][ci] = sv;
                pm[pi] = fmaxf(pm[pi], sv);
            }
        }
    }
    #pragma unroll
    for (int i = 0; i < 4; i++) {
        pm[i] = fmaxf(pm[i], __shfl_xor_sync(0xffffffffu, pm[i], 4));
        pm[i] = fmaxf(pm[i], __shfl_xor_sync(0xffffffffu, pm[i], 8));
        pm[i] = fmaxf(pm[i], __shfl_xor_sync(0xffffffffu, pm[i], 16));
    }
    if (l < 4) {
        red[(2 * l) * 8 + wp]     = pm[0];
        red[(2 * l + 1) * 8 + wp] = pm[1];
        red[(2 * l + 8) * 8 + wp] = pm[2];
        red[(2 * l + 9) * 8 + wp] = pm[3];
    }
    __syncthreads();
    if (tid < 16) {
        float m = red[tid * 8];
        #pragma unroll
        for (int j = 1; j < 8; j++) m = fmaxf(m, red[tid * 8 + j]);
        Gm[tid] = m;
    }
    __syncthreads();

    // ---- exp, partial sums, write P (bf16, slot-paired via shfl) ----
    float gm[4], ps[4] = {0.f, 0.f, 0.f, 0.f};
    #pragma unroll
    for (int i = 0; i < 4; i++)
        gm[i] = Gm[(i >> 1) * 8 + 2 * tig + (i & 1)];
    for (int mi = 0; mi < nmt; mi++) {
        const int m0 = m0s[mi];
        #pragma unroll
        for (int nt = 0; nt < 2; nt++) {
            const int tk0 = nt * 8 + 2 * tig, tk1 = tk0 + 1;
            const float p0 = __expf(sacc[mi][nt][0] - gm[nt * 2]);
            const float p1 = __expf(sacc[mi][nt][1] - gm[nt * 2 + 1]);
            const float p2 = __expf(sacc[mi][nt][2] - gm[nt * 2]);
            const float p3 = __expf(sacc[mi][nt][3] - gm[nt * 2 + 1]);
            const float q0 = __shfl_down_sync(0xffffffffu, p0, 4);
            const float q1 = __shfl_down_sync(0xffffffffu, p1, 4);
            const float q2 = __shfl_down_sync(0xffffffffu, p2, 4);
            const float q3 = __shfl_down_sync(0xffffffffu, p3, 4);
            if (!(gr & 1)) {
                const int pairA = (m0 >> 1) + (gr >> 1);
                const int pairB = pairA + 4;
                Ph[tk0 * PHSTR + pairA] = pack_bf16(p0, q0);
                Ph[tk1 * PHSTR + pairA] = pack_bf16(p1, q1);
                Ph[tk0 * PHSTR + pairB] = pack_bf16(p2, q2);
                Ph[tk1 * PHSTR + pairB] = pack_bf16(p3, q3);
            }
            ps[nt * 2]     += p0 + p2;
            ps[nt * 2 + 1] += p1 + p3;
        }
    }
    #pragma unroll
    for (int i = 0; i < 4; i++) {
        ps[i] += __shfl_xor_sync(0xffffffffu, ps[i], 4);
        ps[i] += __shfl_xor_sync(0xffffffffu, ps[i], 8);
        ps[i] += __shfl_xor_sync(0xffffffffu, ps[i], 16);
    }
    if (l < 4) {
        red[(2 * l) * 8 + wp]     = ps[0];
        red[(2 * l + 1) * 8 + wp] = ps[1];
        red[(2 * l + 8) * 8 + wp] = ps[2];
        red[(2 * l + 9) * 8 + wp] = ps[3];
    }
    __syncthreads();   // P + sums written; all K reads done

    if (tid < 16) {
        float s = 0.f;
        #pragma unroll
        for (int j = 0; j < 8; j++) s += red[tid * 8 + j];
        Ssum[tid] = s;
    }
    // ---- stage V as bf16 slot pairs (overwrites Kh region) ----
    #pragma unroll
    for (int j = 0; j < 5; j++) {
        const int u = tid + 256 * j;                 // 0..1279: (pair, c4)
        const int pr = u >> 3, c = (u & 7) * 4;
        const int s0 = 2 * pr, s1 = s0 + 1;
        const int tl0 = s0 >> 6, rem0 = s0 & 63;
        const int tl1 = s1 >> 6, rem1 = s1 & 63;
        const int tn0 = max(t - 4 + tl0, 0);
        const int tn1 = max(t - 4 + tl1, 0);
        const int tok0 = (tn0 * 16 + h_base + (rem0 >> 3)) * 16 + w_base + (rem0 & 7);
        const int tok1 = (tn1 * 16 + h_base + (rem1 >> 3)) * 16 + w_base + (rem1 & 7);
        const float4 v0 = *(const float4*)&v[(size_t)tok0 * DMODEL + head * DHEAD + c];
        const float4 v1 = *(const float4*)&v[(size_t)tok1 * DMODEL + head * DHEAD + c];
        uint4 w;
        w.x = pack_bf16(v0.x, v1.x);
        w.y = pack_bf16(v0.y, v1.y);
        w.z = pack_bf16(v0.z, v1.z);
        w.w = pack_bf16(v0.w, v1.w);
        *(uint4*)&KVu[pr * VHSTR + c] = w;
    }
    __syncthreads();

    // ---- O = P @ V (bf16): m=16 tok, n=32 ch (4 ntiles), k=320 (2 halves) ---
    const int ntile = wp & 3, khf = wp >> 2;
    const int n0 = ntile * 8;
    float oacc[4] = {0.f, 0.f, 0.f, 0.f};
    #pragma unroll
    for (int j = 0; j < 10; j++) {
        const int kp0 = khf * 80 + j * 8;            // slot-pair base
        uint32_t a[4], b[2];
        a[0] = Ph[gr * PHSTR + kp0 + tig];
        a[1] = Ph[(gr + 8) * PHSTR + kp0 + tig];
        a[2] = Ph[gr * PHSTR + kp0 + 4 + tig];
        a[3] = Ph[(gr + 8) * PHSTR + kp0 + 4 + tig];
        b[0] = KVu[(kp0 + tig) * VHSTR + n0 + gr];
        b[1] = KVu[(kp0 + 4 + tig) * VHSTR + n0 + gr];
        mma_bf16(oacc, a, b);
    }
    if (wp >= 4)
        *(float4*)&redO[(wp - 4) * 128 + l * 4] =
            make_float4(oacc[0], oacc[1], oacc[2], oacc[3]);
    __syncthreads();
    if (wp < 4) {
        const float4 o2 = *(const float4*)&redO[wp * 128 + l * 4];
        oacc[0] += o2.x; oacc[1] += o2.y; oacc[2] += o2.z; oacc[3] += o2.w;
        const float inv0 = 1.f / Ssum[gr];
        const float inv1 = 1.f / Ssum[gr + 8];
        const int tok0 = rinfo[gr] >> 8;
        const int tok1 = rinfo[gr + 8] >> 8;
        const int col = n0 + 2 * tig;
        *(float2*)&out[(size_t)tok0 * DMODEL + head * DHEAD + col] =
            make_float2(oacc[0] * inv0, oacc[1] * inv0);
        *(float2*)&out[(size_t)tok1 * DMODEL + head * DHEAD + col] =
            make_float2(oacc[2] * inv1, oacc[3] * inv1);
    }
}

// ---------------- launch ------------------------------------------------------
extern "C" void kernel_launch(void* const* d_in, const int* in_sizes, int n_in,
                              void* d_out, int out_size) {
    const float* x   = (const float*)d_in[0];
    const float* n1w = (const float*)d_in[1];
    const float* n2w = (const float*)d_in[2];
    const float* wq  = (const float*)d_in[3];
    const float* bq  = (const float*)d_in[4];
    const float* wk  = (const float*)d_in[5];
    const float* bk  = (const float*)d_in[6];
    const float* wv  = (const float*)d_in[7];
    const float* bv  = (const float*)d_in[8];
    const float* wo  = (const float*)d_in[9];
    const float* bo  = (const float*)d_in[10];
    const float* w1  = (const float*)d_in[11];
    const float* w2  = (const float*)d_in[12];
    const float* w3  = (const float*)d_in[13];
    float* out = (float*)d_out;

    float *p_v, *p_at, *p_h, *p_fa, *p_rs1, *p_ssp;
    uint32_t *p_qh, *p_kh, *p_w1h, *p_w2h;
    cudaGetSymbolAddress((void**)&p_v,   g_v);
    cudaGetSymbolAddress((void**)&p_at,  g_at);
    cudaGetSymbolAddress((void**)&p_h,   g_h);
    cudaGetSymbolAddress((void**)&p_fa,  g_fa);
    cudaGetSymbolAddress((void**)&p_rs1, g_rs1);
    cudaGetSymbolAddress((void**)&p_ssp, g_ssp);
    cudaGetSymbolAddress((void**)&p_qh,  g_qh);
    cudaGetSymbolAddress((void**)&p_kh,  g_kh);
    cudaGetSymbolAddress((void**)&p_w1h, g_w1h);
    cudaGetSymbolAddress((void**)&p_w2h, g_w2h);

    const int na_smem = (6400 + 320 + 2624 + 128 + 16 + 16 + 512 + 16) * 4;  // 40128
    static int configured = 0;
    if (!configured) {
        cudaFuncSetAttribute(na3d_v4, cudaFuncAttributeMaxDynamicSharedMemorySize, na_smem);
        configured = 1;
    }

    const dim3 blk(128);

    // 0) convert W1/W2 to bf16 (independent)
    cvt_w12_k<<<(DMODEL / 2) * DFF / 256, 256>>>(w1, w2, p_w1h, p_w2h);

    // 1) rscale1 = rms scale of x
    rms_scale_k<<<NTOK / 8, 256>>>(x, p_rs1);

    // 2) q,k (bf16 packed), v (fp32) = rmsnorm(x) @ {wq,wk,wv} + bias
    gemm_v7<true, true><<<dim3(DMODEL / 64, NTOK / 32, 3), blk>>>(
        x, p_rs1, n1w, wq, wk, wv, bq, bk, bv, nullptr,
        nullptr, nullptr, p_v, p_qh, p_kh, nullptr, DMODEL, DMODEL);

    // 3) neighborhood attention (bf16 tensor-core)
    na3d_v4<<<dim3(128, NHEAD), 256, na_smem>>>(p_qh, p_kh, p_v, p_at);

    // 4) h = x + attn @ wo + bo   (+ per-row sumsq partials of h)
    gemm_v7<false, false><<<dim3(DMODEL / 64, NTOK / 32, 1), blk>>>(
        p_at, nullptr, nullptr, wo, nullptr, nullptr, bo, nullptr, nullptr, x,
        p_h, nullptr, nullptr, nullptr, nullptr, p_ssp, DMODEL, DMODEL);

    // 5) fa = silu(rmsnorm(h)@w1) * (rmsnorm(h)@w2)   (bf16 MMA)
    gate_h<<<dim3(DFF / 64, NTOK / 32), blk>>>(
        p_h, p_ssp, n2w, p_w1h, p_w2h, p_fa, DFF, DMODEL);

    // 6) out = h + fa @ w3
    gemm_v7<false, false><<<dim3(DMODEL / 64, NTOK / 32, 1), blk>>>(
        p_fa, nullptr, nullptr, w3, nullptr, nullptr, nullptr, nullptr, nullptr, p_h,
        out, nullptr, nullptr, nullptr, nullptr, nullptr, DMODEL, DFF);
}